// round 4
// baseline (speedup 1.0000x reference)
#include <cuda_runtime.h>
#include <cuda_fp16.h>

// ---------------------------------------------------------------------------
// LapImage: fused 4-level trilinear grid_sample (align_corners=True)
// Round 4 (= Round 3 re-bench; R3 was an infra double-fail):
// spatial counting-sort of the 3.54M sample points by (z0, y_lvl3, x_lvl3_line)
// so warps gain cache-line locality, then sample in sorted order and scatter
// results. Volumes stay x-pair-packed fp16 (Round 2 layout).
//
// Pipeline (one CUDA graph, 8 kernels):
//   repack -> zero_hist -> hist -> scan1 -> scan2 -> scan3 -> permute -> sample
// ---------------------------------------------------------------------------

#define NPTS   (4 * 96 * 96 * 96)   // 3,538,944
#define PLANE  (96 * 96 * 96)       // 884,736
#define NVOX   2785280              // 32768 + 131072 + 524288 + 2097152
#define NBINS  262144               // 32 z * 256 y * 32 x-lines (lvl3)
#define NBLK   512                  // scan: 512 blocks x 512 elems

__device__ uint4    g_vol[NVOX];      // 44.6 MB pair-packed fp16 volumes
__device__ unsigned g_hist[NBINS];
__device__ unsigned g_off1[NBINS];    // exclusive scan within 512-chunk
__device__ unsigned g_off2[NBLK];     // exclusive chunk offsets
__device__ unsigned g_start[NBINS];   // bin cursors (start offsets, then bumped)
__device__ uint4    g_sorted[NPTS];   // {gx, gy, gz, orig_index} per point

// ---------------- volume repack (Round-2 layout) ---------------------------
__global__ __launch_bounds__(256)
void repack_all_kernel(const float* __restrict__ i0, const float* __restrict__ i1,
                       const float* __restrict__ i2, const float* __restrict__ i3) {
    int i = blockIdx.x * blockDim.x + threadIdx.x;
    if (i >= NVOX) return;

    const float* __restrict__ src;
    int n, base;
    if (i < 32768)        { src = i0; n = 32768;   base = 0;      }
    else if (i < 163840)  { src = i1; n = 131072;  base = 32768;  }
    else if (i < 688128)  { src = i2; n = 524288;  base = 163840; }
    else                  { src = i3; n = 2097152; base = 688128; }

    int li = i - base;
    int j  = min(li + 1, n - 1);   // x+1 neighbor; row-crossing entry never sampled

    __half2 p0 = __halves2half2(__float2half_rn(src[li]),         __float2half_rn(src[n + li]));
    __half2 p1 = __halves2half2(__float2half_rn(src[2 * n + li]), __float2half_rn(src[j]));
    __half2 p2 = __halves2half2(__float2half_rn(src[n + j]),      __float2half_rn(src[2 * n + j]));
    uint4 v;
    v.x = *(unsigned int*)&p0;
    v.y = *(unsigned int*)&p1;
    v.z = *(unsigned int*)&p2;
    v.w = 0u;
    g_vol[i] = v;
}

// ---------------- spatial key: lvl3 cache-line granularity -----------------
__device__ __forceinline__ int point_key(float gx, float gy, float gz) {
    int z0 = min((int)((gz + 1.0f) * 15.5f), 30);
    int y3 = min((int)((gy + 1.0f) * 127.5f), 254);
    int x3 = min((int)((gx + 1.0f) * 127.5f), 254);
    return (z0 * 256 + y3) * 32 + (x3 >> 3);    // 8 pair-entries = 128B line
}

__global__ __launch_bounds__(256)
void zero_hist_kernel() {
    int i = blockIdx.x * blockDim.x + threadIdx.x;
    if (i < NBINS) g_hist[i] = 0u;
}

__global__ __launch_bounds__(256)
void hist_kernel(const float* __restrict__ coords) {
    int p = blockIdx.x * blockDim.x + threadIdx.x;
    if (p >= NPTS) return;
    float gx = coords[3 * p + 0];
    float gy = coords[3 * p + 1];
    float gz = coords[3 * p + 2];
    atomicAdd(&g_hist[point_key(gx, gy, gz)], 1u);
}

// scan stage 1: exclusive scan within each 512-chunk; chunk totals -> g_off2
__global__ __launch_bounds__(512)
void scan1_kernel() {
    __shared__ unsigned s[512];
    int t   = threadIdx.x;
    int idx = blockIdx.x * 512 + t;
    unsigned v = g_hist[idx];
    s[t] = v;
    __syncthreads();
#pragma unroll
    for (int d = 1; d < 512; d <<= 1) {
        unsigned add = (t >= d) ? s[t - d] : 0u;
        __syncthreads();
        s[t] += add;
        __syncthreads();
    }
    g_off1[idx] = s[t] - v;                   // exclusive
    if (t == 511) g_off2[blockIdx.x] = s[t];  // chunk total
}

// scan stage 2: exclusive scan of the 512 chunk totals (single block)
__global__ __launch_bounds__(512)
void scan2_kernel() {
    __shared__ unsigned s[512];
    int t = threadIdx.x;
    unsigned v = g_off2[t];
    s[t] = v;
    __syncthreads();
#pragma unroll
    for (int d = 1; d < 512; d <<= 1) {
        unsigned add = (t >= d) ? s[t - d] : 0u;
        __syncthreads();
        s[t] += add;
        __syncthreads();
    }
    g_off2[t] = s[t] - v;                     // exclusive
}

// scan stage 3: global bin start offsets
__global__ __launch_bounds__(256)
void scan3_kernel() {
    int i = blockIdx.x * blockDim.x + threadIdx.x;
    if (i < NBINS) g_start[i] = g_off1[i] + g_off2[i >> 9];
}

__global__ __launch_bounds__(256)
void permute_kernel(const float* __restrict__ coords) {
    int p = blockIdx.x * blockDim.x + threadIdx.x;
    if (p >= NPTS) return;
    float gx = coords[3 * p + 0];
    float gy = coords[3 * p + 1];
    float gz = coords[3 * p + 2];
    int k = point_key(gx, gy, gz);
    unsigned pos = atomicAdd(&g_start[k], 1u);
    uint4 r;
    r.x = __float_as_uint(gx);
    r.y = __float_as_uint(gy);
    r.z = __float_as_uint(gz);
    r.w = (unsigned)p;
    g_sorted[pos] = r;
}

// ---------------- sampling over sorted points ------------------------------
__device__ __forceinline__ void acc_pair(uint4 q, float w, float wx0, float wx1,
                                         float& ax, float& ay, float& az) {
    float2 f0 = __half22float2(*(__half2*)&q.x);   // c0(x0), c1(x0)
    float2 f1 = __half22float2(*(__half2*)&q.y);   // c2(x0), c0(x1)
    float2 f2 = __half22float2(*(__half2*)&q.z);   // c1(x1), c2(x1)
    ax = fmaf(w, fmaf(f0.x, wx0, f1.y * wx1), ax);
    ay = fmaf(w, fmaf(f0.y, wx0, f2.x * wx1), ay);
    az = fmaf(w, fmaf(f1.x, wx0, f2.y * wx1), az);
}

__global__ __launch_bounds__(256)
void sample_kernel(float* __restrict__ out) {
    int i = blockIdx.x * blockDim.x + threadIdx.x;
    if (i >= NPTS) return;

    uint4 rec = g_sorted[i];
    float gx = __uint_as_float(rec.x);
    float gy = __uint_as_float(rec.y);
    float gz = __uint_as_float(rec.z);
    int   p  = (int)rec.w;

    float iz  = (gz + 1.0f) * 15.5f;
    float z0f = floorf(iz);
    float wz1 = iz - z0f;
    float wz0 = 1.0f - wz1;
    int   z0  = min((int)z0f, 30);
    int   z1  = z0 + 1;

    float ax = 0.0f, ay = 0.0f, az = 0.0f;
    const int offs[4] = {0, 32768, 163840, 688128};

#pragma unroll
    for (int lvl = 0; lvl < 4; ++lvl) {
        const int   HW = 32 << lvl;
        const float sc = 0.5f * (float)(HW - 1);
        const uint4* __restrict__ vol = g_vol + offs[lvl];

        float ix  = (gx + 1.0f) * sc;
        float iy  = (gy + 1.0f) * sc;
        float x0f = floorf(ix);
        float y0f = floorf(iy);
        float wx1 = ix - x0f, wx0 = 1.0f - wx1;
        float wy1 = iy - y0f, wy0 = 1.0f - wy1;
        int x0 = min((int)x0f, HW - 2);
        int y0 = min((int)y0f, HW - 2);
        int y1 = y0 + 1;

        int r00 = (z0 * HW + y0) * HW + x0;
        int r01 = (z0 * HW + y1) * HW + x0;
        int r10 = (z1 * HW + y0) * HW + x0;
        int r11 = (z1 * HW + y1) * HW + x0;

        uint4 q00 = __ldg(vol + r00);
        uint4 q01 = __ldg(vol + r01);
        uint4 q10 = __ldg(vol + r10);
        uint4 q11 = __ldg(vol + r11);

        acc_pair(q00, wz0 * wy0, wx0, wx1, ax, ay, az);
        acc_pair(q01, wz0 * wy1, wx0, wx1, ax, ay, az);
        acc_pair(q10, wz1 * wy0, wx0, wx1, ax, ay, az);
        acc_pair(q11, wz1 * wy1, wx0, wx1, ax, ay, az);
    }

    int b  = p / PLANE;
    int pl = p - b * PLANE;
    float* o = out + (size_t)b * (3 * PLANE) + pl;
    o[0]         = ax;
    o[PLANE]     = ay;
    o[2 * PLANE] = az;
}

extern "C" void kernel_launch(void* const* d_in, const int* in_sizes, int n_in,
                              void* d_out, int out_size) {
    const float* coords = (const float*)d_in[0];
    const float* img0   = (const float*)d_in[1];
    const float* img1   = (const float*)d_in[2];
    const float* img2   = (const float*)d_in[3];
    const float* img3   = (const float*)d_in[4];
    float* out = (float*)d_out;

    repack_all_kernel<<<(NVOX + 255) / 256, 256>>>(img0, img1, img2, img3);
    zero_hist_kernel<<<NBINS / 256, 256>>>();
    hist_kernel<<<NPTS / 256, 256>>>(coords);
    scan1_kernel<<<NBLK, 512>>>();
    scan2_kernel<<<1, 512>>>();
    scan3_kernel<<<NBINS / 256, 256>>>();
    permute_kernel<<<NPTS / 256, 256>>>(coords);
    sample_kernel<<<NPTS / 256, 256>>>(out);
}